// round 1
// baseline (speedup 1.0000x reference)
#include <cuda_runtime.h>
#include <math.h>

// Problem constants
constexpr int BB = 4;
constexpr int LL = 4096;
constexpr int DD = 1024;
constexpr int MM = BB * LL;           // 16384 rows
constexpr int NC = 16;                // scan chunks
constexpr int CL = LL / NC;           // 256 steps per chunk

// Scratch (static device memory; no allocations allowed)
__device__ float g_k[(size_t)MM * DD];
__device__ float g_v[(size_t)MM * DD];
__device__ float g_r[(size_t)MM * DD];          // r, then r*wkv in place
__device__ float g_sa[NC * BB * DD];
__device__ float g_sb[NC * BB * DD];
__device__ float g_ain[NC * BB * DD];
__device__ float g_bin[NC * BB * DD];

// ---------------------------------------------------------------------------
// GEMM: C[m][n] = sum_k A[m][k] * W[n][k]   (fp32, 128x128x8 tile, 8x8/thread)
// AMODE 0: A = x*mix + x_prev*(1-mix)  (token-shift fused into A load)
// AMODE 1: A = plain buffer
// SIG: apply sigmoid in epilogue
// ---------------------------------------------------------------------------
template <int AMODE, bool SIG>
__global__ __launch_bounds__(256)
void gemm_kernel(const float* __restrict__ X,
                 const float* __restrict__ mixv,
                 const float* __restrict__ W,
                 float* __restrict__ C)
{
    constexpr int Bb_M = 128, Bb_N = 128, Bb_K = 8;

    __shared__ float As[Bb_K][Bb_M];
    __shared__ float Ws[Bb_K][Bb_N];

    const int tid = threadIdx.x;          // 256 threads
    const int tx = tid & 15;              // 0..15
    const int ty = tid >> 4;              // 0..15
    const int bm = blockIdx.y * Bb_M;
    const int bn = blockIdx.x * Bb_N;

    const int lr = tid >> 1;              // loader row 0..127
    const int lc = (tid & 1) * 4;         // loader col 0 or 4

    float acc[8][8];
#pragma unroll
    for (int i = 0; i < 8; i++)
#pragma unroll
        for (int j = 0; j < 8; j++) acc[i][j] = 0.0f;

    const int m_ld = bm + lr;
    const int n_ld = bn + lr;

    for (int kt = 0; kt < DD; kt += Bb_K) {
        const int k = kt + lc;

        // ---- load A tile ----
        float4 av;
        if (AMODE == 0) {
            float4 xv = *(const float4*)(X + (size_t)m_ld * DD + k);
            float4 xp = make_float4(0.f, 0.f, 0.f, 0.f);
            const int l = m_ld & (LL - 1);
            if (l != 0)
                xp = *(const float4*)(X + (size_t)(m_ld - 1) * DD + k);
            float4 mv = *(const float4*)(mixv + k);
            av.x = xv.x * mv.x + xp.x * (1.0f - mv.x);
            av.y = xv.y * mv.y + xp.y * (1.0f - mv.y);
            av.z = xv.z * mv.z + xp.z * (1.0f - mv.z);
            av.w = xv.w * mv.w + xp.w * (1.0f - mv.w);
        } else {
            av = *(const float4*)(X + (size_t)m_ld * DD + k);
        }
        As[lc + 0][lr] = av.x;
        As[lc + 1][lr] = av.y;
        As[lc + 2][lr] = av.z;
        As[lc + 3][lr] = av.w;

        // ---- load W tile ----
        float4 wv = *(const float4*)(W + (size_t)n_ld * DD + k);
        Ws[lc + 0][lr] = wv.x;
        Ws[lc + 1][lr] = wv.y;
        Ws[lc + 2][lr] = wv.z;
        Ws[lc + 3][lr] = wv.w;

        __syncthreads();

#pragma unroll
        for (int kk = 0; kk < Bb_K; kk++) {
            float4 a0 = *(const float4*)&As[kk][ty * 8];
            float4 a1 = *(const float4*)&As[kk][ty * 8 + 4];
            float4 b0 = *(const float4*)&Ws[kk][tx * 8];
            float4 b1 = *(const float4*)&Ws[kk][tx * 8 + 4];
            float af[8] = {a0.x, a0.y, a0.z, a0.w, a1.x, a1.y, a1.z, a1.w};
            float bf[8] = {b0.x, b0.y, b0.z, b0.w, b1.x, b1.y, b1.z, b1.w};
#pragma unroll
            for (int i = 0; i < 8; i++)
#pragma unroll
                for (int j = 0; j < 8; j++)
                    acc[i][j] = fmaf(af[i], bf[j], acc[i][j]);
        }
        __syncthreads();
    }

    // ---- epilogue ----
#pragma unroll
    for (int i = 0; i < 8; i++) {
        const int m = bm + ty * 8 + i;
        float* row = C + (size_t)m * DD + bn + tx * 8;
#pragma unroll
        for (int j4 = 0; j4 < 8; j4 += 4) {
            float4 o;
            float v0 = acc[i][j4 + 0], v1 = acc[i][j4 + 1];
            float v2 = acc[i][j4 + 2], v3 = acc[i][j4 + 3];
            if (SIG) {
                v0 = 1.0f / (1.0f + expf(-v0));
                v1 = 1.0f / (1.0f + expf(-v1));
                v2 = 1.0f / (1.0f + expf(-v2));
                v3 = 1.0f / (1.0f + expf(-v3));
            }
            o.x = v0; o.y = v1; o.z = v2; o.w = v3;
            *(float4*)(row + j4) = o;
        }
    }
}

// ---------------------------------------------------------------------------
// WKV scan, chunked (affine recurrence: a' = decay*a + e^k * v ; b' likewise)
// Phase 1: per-chunk partial sums (state starting from 0)
// Phase 2: sequential combine across chunks (per channel)
// Phase 3: within-chunk replay with correct incoming state; writes r*wkv
// ---------------------------------------------------------------------------
__global__ void wkv_phase1(const float* __restrict__ K_,
                           const float* __restrict__ V_,
                           const float* __restrict__ td,
                           float* __restrict__ SA,
                           float* __restrict__ SB)
{
    const int gid = blockIdx.x * blockDim.x + threadIdx.x;   // NC*BB*DD threads
    const int d = gid % DD;
    const int b = (gid / DD) % BB;
    const int c = gid / (DD * BB);

    const float w = -expf(td[d]);
    const float decay = expf(w);

    size_t base = ((size_t)(b * LL + c * CL)) * DD + d;
    float sa = 0.0f, sb = 0.0f;
#pragma unroll 4
    for (int t = 0; t < CL; t++) {
        const float kt = K_[base];
        const float vt = V_[base];
        const float ek = expf(kt);
        sa = decay * sa + ek * vt;
        sb = decay * sb + ek;
        base += DD;
    }
    SA[gid] = sa;
    SB[gid] = sb;
}

__global__ void wkv_phase2(const float* __restrict__ SA,
                           const float* __restrict__ SB,
                           const float* __restrict__ td,
                           float* __restrict__ AIN,
                           float* __restrict__ BIN)
{
    const int gid = blockIdx.x * blockDim.x + threadIdx.x;   // BB*DD threads
    const int d = gid % DD;
    const int b = gid / DD;

    const float w = -expf(td[d]);
    const float dpow = expf(w * (float)CL);

    float a = 0.0f, bs = 0.0f;
#pragma unroll
    for (int c = 0; c < NC; c++) {
        const size_t sidx = ((size_t)c * BB + b) * DD + d;
        AIN[sidx] = a;
        BIN[sidx] = bs;
        a  = dpow * a  + SA[sidx];
        bs = dpow * bs + SB[sidx];
    }
}

__global__ void wkv_phase3(const float* __restrict__ K_,
                           const float* __restrict__ V_,
                           const float* __restrict__ td,
                           const float* __restrict__ tf,
                           const float* __restrict__ AIN,
                           const float* __restrict__ BIN,
                           float* __restrict__ RW)   // in: r, out: r*wkv
{
    const int gid = blockIdx.x * blockDim.x + threadIdx.x;   // NC*BB*DD threads
    const int d = gid % DD;
    const int b = (gid / DD) % BB;
    const int c = gid / (DD * BB);

    const float w = -expf(td[d]);
    const float decay = expf(w);
    const float u = tf[d];

    float a  = AIN[gid];
    float bs = BIN[gid];

    size_t base = ((size_t)(b * LL + c * CL)) * DD + d;
#pragma unroll 4
    for (int t = 0; t < CL; t++) {
        const float kt = K_[base];
        const float vt = V_[base];
        const float eku = expf(u + kt);
        const float wkv = (a + eku * vt) / fmaxf(bs + eku, 1e-6f);
        const float ek = expf(kt);
        RW[base] = RW[base] * wkv;
        a  = decay * a  + ek * vt;
        bs = decay * bs + ek;
        base += DD;
    }
}

// ---------------------------------------------------------------------------
extern "C" void kernel_launch(void* const* d_in, const int* in_sizes, int n_in,
                              void* d_out, int out_size)
{
    const float* x  = (const float*)d_in[0];
    const float* td = (const float*)d_in[1];
    const float* tf = (const float*)d_in[2];
    const float* mk = (const float*)d_in[3];
    const float* mv = (const float*)d_in[4];
    const float* mr = (const float*)d_in[5];
    const float* Wk = (const float*)d_in[6];
    const float* Wv = (const float*)d_in[7];
    const float* Wr = (const float*)d_in[8];
    const float* Wo = (const float*)d_in[9];
    float* out = (float*)d_out;

    float *gk, *gv, *gr, *gsa, *gsb, *gain, *gbin;
    cudaGetSymbolAddress((void**)&gk,   g_k);
    cudaGetSymbolAddress((void**)&gv,   g_v);
    cudaGetSymbolAddress((void**)&gr,   g_r);
    cudaGetSymbolAddress((void**)&gsa,  g_sa);
    cudaGetSymbolAddress((void**)&gsb,  g_sb);
    cudaGetSymbolAddress((void**)&gain, g_ain);
    cudaGetSymbolAddress((void**)&gbin, g_bin);

    const dim3 gg(DD / 128, MM / 128);
    const dim3 tb(256);

    gemm_kernel<0, false><<<gg, tb>>>(x, mk, Wk, gk);
    gemm_kernel<0, false><<<gg, tb>>>(x, mv, Wv, gv);
    gemm_kernel<0, true ><<<gg, tb>>>(x, mr, Wr, gr);

    wkv_phase1<<<(NC * BB * DD) / 256, 256>>>(gk, gv, td, gsa, gsb);
    wkv_phase2<<<(BB * DD) / 256, 256>>>(gsa, gsb, td, gain, gbin);
    wkv_phase3<<<(NC * BB * DD) / 256, 256>>>(gk, gv, td, tf, gain, gbin, gr);

    gemm_kernel<1, false><<<gg, tb>>>(gr, nullptr, Wo, out);
}

// round 3
// speedup vs baseline: 2.7753x; 2.7753x over previous
#include <cuda_runtime.h>
#include <cuda_bf16.h>
#include <math.h>
#include <cstdint>
#include <cstddef>

// Problem constants
constexpr int BB = 4;
constexpr int LL = 4096;
constexpr int DD = 1024;
constexpr int MM = BB * LL;           // 16384 rows
constexpr int NC = 16;                // scan chunks
constexpr int CL = LL / NC;           // 256 steps per chunk

// ---------------------------------------------------------------------------
// Static device scratch (no allocations allowed)
// ---------------------------------------------------------------------------
__device__ float g_k[(size_t)MM * DD];
__device__ float g_v[(size_t)MM * DD];
__device__ float g_r[(size_t)MM * DD];

__device__ __nv_bfloat16 g_xkh[(size_t)MM * DD];
__device__ __nv_bfloat16 g_xkl[(size_t)MM * DD];
__device__ __nv_bfloat16 g_xvh[(size_t)MM * DD];
__device__ __nv_bfloat16 g_xvl[(size_t)MM * DD];
__device__ __nv_bfloat16 g_xrh[(size_t)MM * DD];
__device__ __nv_bfloat16 g_xrl[(size_t)MM * DD];
__device__ __nv_bfloat16 g_rwh[(size_t)MM * DD];
__device__ __nv_bfloat16 g_rwl[(size_t)MM * DD];

__device__ __nv_bfloat16 g_wh[4][(size_t)DD * DD];
__device__ __nv_bfloat16 g_wl[4][(size_t)DD * DD];

__device__ float g_sa[NC * BB * DD];
__device__ float g_sb[NC * BB * DD];
__device__ float g_ain[NC * BB * DD];
__device__ float g_bin[NC * BB * DD];

// ---------------------------------------------------------------------------
// PTX helpers (arch-portable: cp.async / ldmatrix / mma.sync)
// ---------------------------------------------------------------------------
__device__ __forceinline__ uint32_t smem_u32(const void* p) {
    uint32_t a;
    asm("{ .reg .u64 t; cvta.to.shared.u64 t, %1; cvt.u32.u64 %0, t; }"
        : "=r"(a) : "l"(p));
    return a;
}

__device__ __forceinline__ void cp16(uint32_t dst, const void* src) {
    asm volatile("cp.async.cg.shared.global [%0], [%1], 16;"
                 :: "r"(dst), "l"(src) : "memory");
}

__device__ __forceinline__ void cp_commit() {
    asm volatile("cp.async.commit_group;" ::: "memory");
}

template <int N>
__device__ __forceinline__ void cp_wait() {
    asm volatile("cp.async.wait_group %0;" :: "n"(N) : "memory");
}

__device__ __forceinline__ void ldsm4(uint32_t* r, uint32_t addr) {
    asm volatile("ldmatrix.sync.aligned.m8n8.x4.shared.b16 {%0,%1,%2,%3}, [%4];"
                 : "=r"(r[0]), "=r"(r[1]), "=r"(r[2]), "=r"(r[3]) : "r"(addr));
}

__device__ __forceinline__ void mma_bf16(float* d, const uint32_t* a, const uint32_t* b) {
    asm volatile(
        "mma.sync.aligned.m16n8k16.row.col.f32.bf16.bf16.f32 "
        "{%0,%1,%2,%3}, {%4,%5,%6,%7}, {%8,%9}, {%0,%1,%2,%3};"
        : "+f"(d[0]), "+f"(d[1]), "+f"(d[2]), "+f"(d[3])
        : "r"(a[0]), "r"(a[1]), "r"(a[2]), "r"(a[3]), "r"(b[0]), "r"(b[1]));
}

__device__ __forceinline__ void split1(float a, __nv_bfloat16& h, __nv_bfloat16& l) {
    h = __float2bfloat16(a);
    l = __float2bfloat16(a - __bfloat162float(h));
}

// Swizzled smem offset for a [128 x 32] bf16 tile (rows of 4 x 16B chunks).
// 128B "lines" hold two rows; 8 chunk-positions per line XORed with line&7.
// Conflict-free for ldmatrix (8 consecutive rows, fixed chunk col).
__device__ __forceinline__ uint32_t phys(int r, int c) {
    return (uint32_t)((r >> 1) * 128 + ((((r & 1) * 4 + c) ^ ((r >> 1) & 7)) * 16));
}

// ---------------------------------------------------------------------------
// bf16 split GEMM via mma.sync:  C[m][n] = sum_k A[m][k]*W[n][k]
//   C = Ah*Wh + Al*Wh + Ah*Wl   (3 HMMA passes, fp32 accum)
// CTA tile 128x128, BK=32, 256 threads (8 warps, 2M x 4N), double-buffered.
// ---------------------------------------------------------------------------
constexpr int TILE_BYTES = 128 * 32 * 2;           // 8192
constexpr int OFF_AH = 0;
constexpr int OFF_AL = TILE_BYTES;
constexpr int OFF_WH = 2 * TILE_BYTES;
constexpr int OFF_WL = 3 * TILE_BYTES;
constexpr int STAGE_BYTES = 4 * TILE_BYTES;        // 32768
constexpr int GEMM_SMEM_BYTES = 2 * STAGE_BYTES;   // 65536
constexpr int NSTAGE = DD / 32;                    // 32

template <bool SIG>
__global__ void __launch_bounds__(256, 2)
gemm_bf16(const __nv_bfloat16* __restrict__ Ah, const __nv_bfloat16* __restrict__ Al,
          const __nv_bfloat16* __restrict__ Wh, const __nv_bfloat16* __restrict__ Wl,
          float* __restrict__ C)
{
    extern __shared__ char smem[];
    const uint32_t sb = smem_u32(smem);
    const int tid = threadIdx.x;
    const int wid = tid >> 5;
    const int l   = tid & 31;
    const int wm  = wid & 1;          // 0..1 (M)
    const int wn  = wid >> 1;         // 0..3 (N)
    const int bm  = blockIdx.y * 128;
    const int bn  = blockIdx.x * 128;

    // ---- loader mapping: each thread copies 2 x 16B chunks per tile ----
    const int lr = tid >> 1;                   // 0..127
    const int lc0 = (tid & 1) * 2;             // chunk 0 or 2
    const size_t arow = (size_t)(bm + lr) * DD;
    const size_t wrow = (size_t)(bn + lr) * DD;
    const uint32_t sw0 = phys(lr, lc0);
    const uint32_t sw1 = phys(lr, lc0 + 1);

    float acc[4][4][4];
#pragma unroll
    for (int i = 0; i < 4; i++)
#pragma unroll
        for (int j = 0; j < 4; j++)
#pragma unroll
            for (int e = 0; e < 4; e++) acc[i][j][e] = 0.0f;

    auto load_stage = [&](int buf, int kc) {
        const uint32_t base = sb + buf * STAGE_BYTES;
        const __nv_bfloat16* pa_h = Ah + arow + kc + lc0 * 8;
        const __nv_bfloat16* pa_l = Al + arow + kc + lc0 * 8;
        const __nv_bfloat16* pw_h = Wh + wrow + kc + lc0 * 8;
        const __nv_bfloat16* pw_l = Wl + wrow + kc + lc0 * 8;
        cp16(base + OFF_AH + sw0, pa_h);
        cp16(base + OFF_AH + sw1, pa_h + 8);
        cp16(base + OFF_AL + sw0, pa_l);
        cp16(base + OFF_AL + sw1, pa_l + 8);
        cp16(base + OFF_WH + sw0, pw_h);
        cp16(base + OFF_WH + sw1, pw_h + 8);
        cp16(base + OFF_WL + sw0, pw_l);
        cp16(base + OFF_WL + sw1, pw_l + 8);
    };

    // ---- ldmatrix lane-address components ----
    // A: lanes 0-7 m0-7/chunk0, 8-15 m8-15/chunk0, 16-23 m0-7/chunk1, 24-31 m8-15/chunk1
    const int ra = wm * 64 + (l & 7) + ((l >> 3) & 1) * 8;   // + mt*16
    const int ca = (l >> 4) & 1;                              // + ks*2
    // B: lanes 0-7 n0-7/chunk0, 8-15 n0-7/chunk1, 16-23 n8-15/chunk0, 24-31 n8-15/chunk1
    const int rb = wn * 32 + (l & 7) + ((l >> 4) & 1) * 8;   // + nt2*16
    const int cb = (l >> 3) & 1;                              // + ks*2

    load_stage(0, 0);
    cp_commit();

    for (int s = 0; s < NSTAGE; s++) {
        if (s + 1 < NSTAGE) load_stage((s + 1) & 1, (s + 1) * 32);
        cp_commit();
        cp_wait<1>();
        __syncthreads();

        const uint32_t base = sb + (s & 1) * STAGE_BYTES;
#pragma unroll
        for (int ks = 0; ks < 2; ks++) {
            uint32_t ah[16], al[16], wh8[8], wl8[8];
#pragma unroll
            for (int mt = 0; mt < 4; mt++) {
                const uint32_t off = phys(ra + mt * 16, ks * 2 + ca);
                ldsm4(ah + mt * 4, base + OFF_AH + off);
                ldsm4(al + mt * 4, base + OFF_AL + off);
            }
#pragma unroll
            for (int nt2 = 0; nt2 < 2; nt2++) {
                const uint32_t off = phys(rb + nt2 * 16, ks * 2 + cb);
                ldsm4(wh8 + nt2 * 4, base + OFF_WH + off);
                ldsm4(wl8 + nt2 * 4, base + OFF_WL + off);
            }
#pragma unroll
            for (int mt = 0; mt < 4; mt++)
#pragma unroll
                for (int nt = 0; nt < 4; nt++) {
                    mma_bf16(acc[mt][nt], ah + mt * 4, wh8 + nt * 2);
                    mma_bf16(acc[mt][nt], ah + mt * 4, wl8 + nt * 2);
                    mma_bf16(acc[mt][nt], al + mt * 4, wh8 + nt * 2);
                }
        }
        __syncthreads();
    }

    // ---- epilogue ----
    const int er = l >> 2;            // 0..7
    const int ec = (l & 3) * 2;       // 0,2,4,6
#pragma unroll
    for (int mt = 0; mt < 4; mt++) {
#pragma unroll
        for (int nt = 0; nt < 4; nt++) {
            const int m0 = bm + wm * 64 + mt * 16 + er;
            const int n0 = bn + wn * 32 + nt * 8 + ec;
            float v0 = acc[mt][nt][0], v1 = acc[mt][nt][1];
            float v2 = acc[mt][nt][2], v3 = acc[mt][nt][3];
            if (SIG) {
                v0 = 1.0f / (1.0f + __expf(-v0));
                v1 = 1.0f / (1.0f + __expf(-v1));
                v2 = 1.0f / (1.0f + __expf(-v2));
                v3 = 1.0f / (1.0f + __expf(-v3));
            }
            *(float2*)(C + (size_t)m0 * DD + n0)       = make_float2(v0, v1);
            *(float2*)(C + (size_t)(m0 + 8) * DD + n0) = make_float2(v2, v3);
        }
    }
}

// ---------------------------------------------------------------------------
// Conversion: token-shift mix + bf16 hi/lo split for the three projections
// ---------------------------------------------------------------------------
__global__ void conv_x(const float* __restrict__ x,
                       const float* __restrict__ mk, const float* __restrict__ mv,
                       const float* __restrict__ mr,
                       __nv_bfloat16* __restrict__ kh, __nv_bfloat16* __restrict__ kl,
                       __nv_bfloat16* __restrict__ vh, __nv_bfloat16* __restrict__ vl,
                       __nv_bfloat16* __restrict__ rh, __nv_bfloat16* __restrict__ rl)
{
    const size_t gid = (size_t)blockIdx.x * blockDim.x + threadIdx.x;
    const size_t idx = gid * 4;
    const int d = (int)(idx % DD);
    const size_t m = idx / DD;
    const int lpos = (int)(m & (LL - 1));

    const float4 xc = *(const float4*)(x + idx);
    float4 xp = make_float4(0.f, 0.f, 0.f, 0.f);
    if (lpos != 0) xp = *(const float4*)(x + idx - DD);

    const float xcv[4] = {xc.x, xc.y, xc.z, xc.w};
    const float xpv[4] = {xp.x, xp.y, xp.z, xp.w};

    const float* mixes[3] = {mk, mv, mr};
    __nv_bfloat16* outh[3] = {kh, vh, rh};
    __nv_bfloat16* outl[3] = {kl, vl, rl};

#pragma unroll
    for (int s = 0; s < 3; s++) {
        const float4 mx = *(const float4*)(mixes[s] + d);
        const float mxv[4] = {mx.x, mx.y, mx.z, mx.w};
        unsigned short hh[4], ll2[4];
#pragma unroll
        for (int j = 0; j < 4; j++) {
            const float a = xcv[j] * mxv[j] + xpv[j] * (1.0f - mxv[j]);
            __nv_bfloat16 h, lo;
            split1(a, h, lo);
            hh[j] = __bfloat16_as_ushort(h);
            ll2[j] = __bfloat16_as_ushort(lo);
        }
        *(ushort4*)(outh[s] + idx) = make_ushort4(hh[0], hh[1], hh[2], hh[3]);
        *(ushort4*)(outl[s] + idx) = make_ushort4(ll2[0], ll2[1], ll2[2], ll2[3]);
    }
}

__global__ void conv_w(const float* __restrict__ W,
                       __nv_bfloat16* __restrict__ Wh, __nv_bfloat16* __restrict__ Wl)
{
    const size_t gid = (size_t)blockIdx.x * blockDim.x + threadIdx.x;
    const size_t idx = gid * 4;
    const float4 w4 = *(const float4*)(W + idx);
    const float wv[4] = {w4.x, w4.y, w4.z, w4.w};
    unsigned short hh[4], ll2[4];
#pragma unroll
    for (int j = 0; j < 4; j++) {
        __nv_bfloat16 h, lo;
        split1(wv[j], h, lo);
        hh[j] = __bfloat16_as_ushort(h);
        ll2[j] = __bfloat16_as_ushort(lo);
    }
    *(ushort4*)(Wh + idx) = make_ushort4(hh[0], hh[1], hh[2], hh[3]);
    *(ushort4*)(Wl + idx) = make_ushort4(ll2[0], ll2[1], ll2[2], ll2[3]);
}

// ---------------------------------------------------------------------------
// WKV scan (chunk-parallel affine recurrence)
// ---------------------------------------------------------------------------
__global__ void wkv_phase1(const float* __restrict__ K_,
                           const float* __restrict__ V_,
                           const float* __restrict__ td,
                           float* __restrict__ SA,
                           float* __restrict__ SB)
{
    const int gid = blockIdx.x * blockDim.x + threadIdx.x;
    const int d = gid % DD;
    const int b = (gid / DD) % BB;
    const int c = gid / (DD * BB);

    const float w = -expf(td[d]);
    const float decay = expf(w);

    size_t base = ((size_t)(b * LL + c * CL)) * DD + d;
    float sa = 0.0f, sb = 0.0f;
#pragma unroll 4
    for (int t = 0; t < CL; t++) {
        const float kt = K_[base];
        const float vt = V_[base];
        const float ek = expf(kt);
        sa = decay * sa + ek * vt;
        sb = decay * sb + ek;
        base += DD;
    }
    SA[gid] = sa;
    SB[gid] = sb;
}

__global__ void wkv_phase2(const float* __restrict__ SA,
                           const float* __restrict__ SB,
                           const float* __restrict__ td,
                           float* __restrict__ AIN,
                           float* __restrict__ BIN)
{
    const int gid = blockIdx.x * blockDim.x + threadIdx.x;
    const int d = gid % DD;
    const int b = gid / DD;

    const float w = -expf(td[d]);
    const float dpow = expf(w * (float)CL);

    float a = 0.0f, bs = 0.0f;
#pragma unroll
    for (int c = 0; c < NC; c++) {
        const size_t sidx = ((size_t)c * BB + b) * DD + d;
        AIN[sidx] = a;
        BIN[sidx] = bs;
        a  = dpow * a  + SA[sidx];
        bs = dpow * bs + SB[sidx];
    }
}

__global__ void wkv_phase3(const float* __restrict__ K_,
                           const float* __restrict__ V_,
                           const float* __restrict__ td,
                           const float* __restrict__ tf,
                           const float* __restrict__ AIN,
                           const float* __restrict__ BIN,
                           const float* __restrict__ R,
                           __nv_bfloat16* __restrict__ RWH,
                           __nv_bfloat16* __restrict__ RWL)
{
    const int gid = blockIdx.x * blockDim.x + threadIdx.x;
    const int d = gid % DD;
    const int b = (gid / DD) % BB;
    const int c = gid / (DD * BB);

    const float w = -expf(td[d]);
    const float decay = expf(w);
    const float u = tf[d];

    float a  = AIN[gid];
    float bs = BIN[gid];

    size_t base = ((size_t)(b * LL + c * CL)) * DD + d;
#pragma unroll 4
    for (int t = 0; t < CL; t++) {
        const float kt = K_[base];
        const float vt = V_[base];
        const float eku = expf(u + kt);
        const float wkv = (a + eku * vt) / fmaxf(bs + eku, 1e-6f);
        const float ek = expf(kt);
        const float rw = R[base] * wkv;
        __nv_bfloat16 h, lo;
        split1(rw, h, lo);
        RWH[base] = h;
        RWL[base] = lo;
        a  = decay * a  + ek * vt;
        bs = decay * bs + ek;
        base += DD;
    }
}

// ---------------------------------------------------------------------------
extern "C" void kernel_launch(void* const* d_in, const int* in_sizes, int n_in,
                              void* d_out, int out_size)
{
    const float* x  = (const float*)d_in[0];
    const float* td = (const float*)d_in[1];
    const float* tf = (const float*)d_in[2];
    const float* mk = (const float*)d_in[3];
    const float* mv = (const float*)d_in[4];
    const float* mr = (const float*)d_in[5];
    const float* Wk = (const float*)d_in[6];
    const float* Wv = (const float*)d_in[7];
    const float* Wr = (const float*)d_in[8];
    const float* Wo = (const float*)d_in[9];
    float* out = (float*)d_out;

    float *gk, *gv, *gr, *gsa, *gsb, *gain, *gbin;
    __nv_bfloat16 *xkh, *xkl, *xvh, *xvl, *xrh, *xrl, *rwh, *rwl, *wh, *wl;
    cudaGetSymbolAddress((void**)&gk,   g_k);
    cudaGetSymbolAddress((void**)&gv,   g_v);
    cudaGetSymbolAddress((void**)&gr,   g_r);
    cudaGetSymbolAddress((void**)&gsa,  g_sa);
    cudaGetSymbolAddress((void**)&gsb,  g_sb);
    cudaGetSymbolAddress((void**)&gain, g_ain);
    cudaGetSymbolAddress((void**)&gbin, g_bin);
    cudaGetSymbolAddress((void**)&xkh,  g_xkh);
    cudaGetSymbolAddress((void**)&xkl,  g_xkl);
    cudaGetSymbolAddress((void**)&xvh,  g_xvh);
    cudaGetSymbolAddress((void**)&xvl,  g_xvl);
    cudaGetSymbolAddress((void**)&xrh,  g_xrh);
    cudaGetSymbolAddress((void**)&xrl,  g_xrl);
    cudaGetSymbolAddress((void**)&rwh,  g_rwh);
    cudaGetSymbolAddress((void**)&rwl,  g_rwl);
    cudaGetSymbolAddress((void**)&wh,   g_wh);
    cudaGetSymbolAddress((void**)&wl,   g_wl);

    cudaFuncSetAttribute(gemm_bf16<false>,
                         cudaFuncAttributeMaxDynamicSharedMemorySize, GEMM_SMEM_BYTES);
    cudaFuncSetAttribute(gemm_bf16<true>,
                         cudaFuncAttributeMaxDynamicSharedMemorySize, GEMM_SMEM_BYTES);

    const size_t WSTRIDE = (size_t)DD * DD;

    // conversions
    conv_x<<<(int)(((size_t)MM * DD / 4) / 256), 256>>>(x, mk, mv, mr,
                                                        xkh, xkl, xvh, xvl, xrh, xrl);
    conv_w<<<(int)((WSTRIDE / 4) / 256), 256>>>(Wk, wh + 0 * WSTRIDE, wl + 0 * WSTRIDE);
    conv_w<<<(int)((WSTRIDE / 4) / 256), 256>>>(Wv, wh + 1 * WSTRIDE, wl + 1 * WSTRIDE);
    conv_w<<<(int)((WSTRIDE / 4) / 256), 256>>>(Wr, wh + 2 * WSTRIDE, wl + 2 * WSTRIDE);
    conv_w<<<(int)((WSTRIDE / 4) / 256), 256>>>(Wo, wh + 3 * WSTRIDE, wl + 3 * WSTRIDE);

    const dim3 gg(DD / 128, MM / 128);

    // projections
    gemm_bf16<false><<<gg, 256, GEMM_SMEM_BYTES>>>(xkh, xkl, wh + 0 * WSTRIDE, wl + 0 * WSTRIDE, gk);
    gemm_bf16<false><<<gg, 256, GEMM_SMEM_BYTES>>>(xvh, xvl, wh + 1 * WSTRIDE, wl + 1 * WSTRIDE, gv);
    gemm_bf16<true ><<<gg, 256, GEMM_SMEM_BYTES>>>(xrh, xrl, wh + 2 * WSTRIDE, wl + 2 * WSTRIDE, gr);

    // wkv scan
    wkv_phase1<<<(NC * BB * DD) / 256, 256>>>(gk, gv, td, gsa, gsb);
    wkv_phase2<<<(BB * DD) / 256, 256>>>(gsa, gsb, td, gain, gbin);
    wkv_phase3<<<(NC * BB * DD) / 256, 256>>>(gk, gv, td, tf, gain, gbin, gr, rwh, rwl);

    // output projection
    gemm_bf16<false><<<gg, 256, GEMM_SMEM_BYTES>>>(rwh, rwl, wh + 3 * WSTRIDE, wl + 3 * WSTRIDE, out);
}

// round 4
// speedup vs baseline: 2.8001x; 1.0089x over previous
#include <cuda_runtime.h>
#include <cuda_bf16.h>
#include <math.h>
#include <cstdint>
#include <cstddef>

// Problem constants
constexpr int BB = 4;
constexpr int LL = 4096;
constexpr int DD = 1024;
constexpr int MM = BB * LL;           // 16384 rows
constexpr int NC = 64;                // scan chunks
constexpr int CL = LL / NC;           // 64 steps per chunk

// ---------------------------------------------------------------------------
// Static device scratch (no allocations allowed)
// ---------------------------------------------------------------------------
__device__ float g_k[(size_t)MM * DD];
__device__ float g_v[(size_t)MM * DD];
__device__ float g_r[(size_t)MM * DD];

__device__ __nv_bfloat16 g_xkh[(size_t)MM * DD];
__device__ __nv_bfloat16 g_xkl[(size_t)MM * DD];
__device__ __nv_bfloat16 g_xvh[(size_t)MM * DD];
__device__ __nv_bfloat16 g_xvl[(size_t)MM * DD];
__device__ __nv_bfloat16 g_xrh[(size_t)MM * DD];
__device__ __nv_bfloat16 g_xrl[(size_t)MM * DD];
__device__ __nv_bfloat16 g_rwh[(size_t)MM * DD];
__device__ __nv_bfloat16 g_rwl[(size_t)MM * DD];

__device__ __nv_bfloat16 g_wh[4][(size_t)DD * DD];
__device__ __nv_bfloat16 g_wl[4][(size_t)DD * DD];

__device__ float g_sa[NC * BB * DD];
__device__ float g_sb[NC * BB * DD];
__device__ float g_ain[NC * BB * DD];
__device__ float g_bin[NC * BB * DD];

// ---------------------------------------------------------------------------
// PTX helpers (arch-portable: cp.async / ldmatrix / mma.sync)
// ---------------------------------------------------------------------------
__device__ __forceinline__ uint32_t smem_u32(const void* p) {
    uint32_t a;
    asm("{ .reg .u64 t; cvta.to.shared.u64 t, %1; cvt.u32.u64 %0, t; }"
        : "=r"(a) : "l"(p));
    return a;
}

__device__ __forceinline__ void cp16(uint32_t dst, const void* src) {
    asm volatile("cp.async.cg.shared.global [%0], [%1], 16;"
                 :: "r"(dst), "l"(src) : "memory");
}

__device__ __forceinline__ void cp_commit() {
    asm volatile("cp.async.commit_group;" ::: "memory");
}

template <int N>
__device__ __forceinline__ void cp_wait() {
    asm volatile("cp.async.wait_group %0;" :: "n"(N) : "memory");
}

__device__ __forceinline__ void ldsm4(uint32_t* r, uint32_t addr) {
    asm volatile("ldmatrix.sync.aligned.m8n8.x4.shared.b16 {%0,%1,%2,%3}, [%4];"
                 : "=r"(r[0]), "=r"(r[1]), "=r"(r[2]), "=r"(r[3]) : "r"(addr));
}

__device__ __forceinline__ void mma_bf16(float* d, const uint32_t* a, const uint32_t* b) {
    asm volatile(
        "mma.sync.aligned.m16n8k16.row.col.f32.bf16.bf16.f32 "
        "{%0,%1,%2,%3}, {%4,%5,%6,%7}, {%8,%9}, {%0,%1,%2,%3};"
        : "+f"(d[0]), "+f"(d[1]), "+f"(d[2]), "+f"(d[3])
        : "r"(a[0]), "r"(a[1]), "r"(a[2]), "r"(a[3]), "r"(b[0]), "r"(b[1]));
}

__device__ __forceinline__ void split1(float a, __nv_bfloat16& h, __nv_bfloat16& l) {
    h = __float2bfloat16(a);
    l = __float2bfloat16(a - __bfloat162float(h));
}

// Swizzled smem offset for a [128 x 32] bf16 tile (rows of 4 x 16B chunks).
// 128B lines hold two rows; 8 chunk-positions per line XORed with line&7.
// Conflict-free for ldmatrix (8 consecutive rows, fixed chunk col).
__device__ __forceinline__ uint32_t phys(int r, int c) {
    return (uint32_t)((r >> 1) * 128 + ((((r & 1) * 4 + c) ^ ((r >> 1) & 7)) * 16));
}

// ---------------------------------------------------------------------------
// bf16 split GEMM via mma.sync:  C[m][n] = sum_k A[m][k]*W[n][k]
//   C = Ah*Wh + Al*Wh + Ah*Wl   (3 HMMA passes, fp32 accum)
// CTA tile 128x128, BK=32, 256 threads (8 warps, 2M x 4N).
// 4-stage cp.async ring (128KB smem, 1 CTA/SM) to hide L2/DRAM latency.
// ---------------------------------------------------------------------------
constexpr int TILE_BYTES = 128 * 32 * 2;           // 8192
constexpr int OFF_AH = 0;
constexpr int OFF_AL = TILE_BYTES;
constexpr int OFF_WH = 2 * TILE_BYTES;
constexpr int OFF_WL = 3 * TILE_BYTES;
constexpr int STAGE_BYTES = 4 * TILE_BYTES;        // 32768
constexpr int PIPE = 4;
constexpr int GEMM_SMEM_BYTES = PIPE * STAGE_BYTES;  // 131072
constexpr int NSTAGE = DD / 32;                    // 32

template <bool SIG>
__global__ void __launch_bounds__(256, 1)
gemm_bf16(const __nv_bfloat16* __restrict__ Ah, const __nv_bfloat16* __restrict__ Al,
          const __nv_bfloat16* __restrict__ Wh, const __nv_bfloat16* __restrict__ Wl,
          float* __restrict__ C)
{
    extern __shared__ char smem[];
    const uint32_t sb = smem_u32(smem);
    const int tid = threadIdx.x;
    const int wid = tid >> 5;
    const int l   = tid & 31;
    const int wm  = wid & 1;          // 0..1 (M)
    const int wn  = wid >> 1;         // 0..3 (N)
    const int bm  = blockIdx.y * 128;
    const int bn  = blockIdx.x * 128;

    // ---- loader mapping: each thread copies 2 x 16B chunks per tile ----
    const int lr = tid >> 1;                   // 0..127
    const int lc0 = (tid & 1) * 2;             // chunk 0 or 2
    const size_t arow = (size_t)(bm + lr) * DD;
    const size_t wrow = (size_t)(bn + lr) * DD;
    const uint32_t sw0 = phys(lr, lc0);
    const uint32_t sw1 = phys(lr, lc0 + 1);

    float acc[4][4][4];
#pragma unroll
    for (int i = 0; i < 4; i++)
#pragma unroll
        for (int j = 0; j < 4; j++)
#pragma unroll
            for (int e = 0; e < 4; e++) acc[i][j][e] = 0.0f;

    auto load_stage = [&](int buf, int kc) {
        const uint32_t base = sb + buf * STAGE_BYTES;
        const __nv_bfloat16* pa_h = Ah + arow + kc + lc0 * 8;
        const __nv_bfloat16* pa_l = Al + arow + kc + lc0 * 8;
        const __nv_bfloat16* pw_h = Wh + wrow + kc + lc0 * 8;
        const __nv_bfloat16* pw_l = Wl + wrow + kc + lc0 * 8;
        cp16(base + OFF_AH + sw0, pa_h);
        cp16(base + OFF_AH + sw1, pa_h + 8);
        cp16(base + OFF_AL + sw0, pa_l);
        cp16(base + OFF_AL + sw1, pa_l + 8);
        cp16(base + OFF_WH + sw0, pw_h);
        cp16(base + OFF_WH + sw1, pw_h + 8);
        cp16(base + OFF_WL + sw0, pw_l);
        cp16(base + OFF_WL + sw1, pw_l + 8);
    };

    // ---- ldmatrix lane-address components ----
    const int ra = wm * 64 + (l & 7) + ((l >> 3) & 1) * 8;   // + mt*16
    const int ca = (l >> 4) & 1;                              // + ks*2
    const int rb = wn * 32 + (l & 7) + ((l >> 4) & 1) * 8;   // + nt2*16
    const int cb = (l >> 3) & 1;                              // + ks*2

    // ---- preload 3 stages ----
#pragma unroll
    for (int i = 0; i < PIPE - 1; i++) {
        load_stage(i, i * 32);
        cp_commit();
    }

    for (int s = 0; s < NSTAGE; s++) {
        cp_wait<PIPE - 2>();          // stage s complete (<= PIPE-2 pending)
        __syncthreads();              // make all threads' copies visible

        // issue next load immediately (hidden behind this stage's compute)
        if (s + PIPE - 1 < NSTAGE)
            load_stage((s + PIPE - 1) & (PIPE - 1), (s + PIPE - 1) * 32);
        cp_commit();

        const uint32_t base = sb + (s & (PIPE - 1)) * STAGE_BYTES;
#pragma unroll
        for (int ks = 0; ks < 2; ks++) {
            uint32_t ah[16], al[16], wh8[8], wl8[8];
#pragma unroll
            for (int mt = 0; mt < 4; mt++) {
                const uint32_t off = phys(ra + mt * 16, ks * 2 + ca);
                ldsm4(ah + mt * 4, base + OFF_AH + off);
                ldsm4(al + mt * 4, base + OFF_AL + off);
            }
#pragma unroll
            for (int nt2 = 0; nt2 < 2; nt2++) {
                const uint32_t off = phys(rb + nt2 * 16, ks * 2 + cb);
                ldsm4(wh8 + nt2 * 4, base + OFF_WH + off);
                ldsm4(wl8 + nt2 * 4, base + OFF_WL + off);
            }
#pragma unroll
            for (int mt = 0; mt < 4; mt++)
#pragma unroll
                for (int nt = 0; nt < 4; nt++) {
                    mma_bf16(acc[mt][nt], ah + mt * 4, wh8 + nt * 2);
                    mma_bf16(acc[mt][nt], ah + mt * 4, wl8 + nt * 2);
                    mma_bf16(acc[mt][nt], al + mt * 4, wh8 + nt * 2);
                }
        }
    }

    // ---- epilogue ----
    const int er = l >> 2;            // 0..7
    const int ec = (l & 3) * 2;       // 0,2,4,6
#pragma unroll
    for (int mt = 0; mt < 4; mt++) {
#pragma unroll
        for (int nt = 0; nt < 4; nt++) {
            const int m0 = bm + wm * 64 + mt * 16 + er;
            const int n0 = bn + wn * 32 + nt * 8 + ec;
            float v0 = acc[mt][nt][0], v1 = acc[mt][nt][1];
            float v2 = acc[mt][nt][2], v3 = acc[mt][nt][3];
            if (SIG) {
                v0 = 1.0f / (1.0f + __expf(-v0));
                v1 = 1.0f / (1.0f + __expf(-v1));
                v2 = 1.0f / (1.0f + __expf(-v2));
                v3 = 1.0f / (1.0f + __expf(-v3));
            }
            *(float2*)(C + (size_t)m0 * DD + n0)       = make_float2(v0, v1);
            *(float2*)(C + (size_t)(m0 + 8) * DD + n0) = make_float2(v2, v3);
        }
    }
}

// ---------------------------------------------------------------------------
// Conversion: token-shift mix + bf16 hi/lo split for the three projections
// ---------------------------------------------------------------------------
__global__ void conv_x(const float* __restrict__ x,
                       const float* __restrict__ mk, const float* __restrict__ mv,
                       const float* __restrict__ mr,
                       __nv_bfloat16* __restrict__ kh, __nv_bfloat16* __restrict__ kl,
                       __nv_bfloat16* __restrict__ vh, __nv_bfloat16* __restrict__ vl,
                       __nv_bfloat16* __restrict__ rh, __nv_bfloat16* __restrict__ rl)
{
    const size_t gid = (size_t)blockIdx.x * blockDim.x + threadIdx.x;
    const size_t idx = gid * 4;
    const int d = (int)(idx % DD);
    const size_t m = idx / DD;
    const int lpos = (int)(m & (LL - 1));

    const float4 xc = *(const float4*)(x + idx);
    float4 xp = make_float4(0.f, 0.f, 0.f, 0.f);
    if (lpos != 0) xp = *(const float4*)(x + idx - DD);

    const float xcv[4] = {xc.x, xc.y, xc.z, xc.w};
    const float xpv[4] = {xp.x, xp.y, xp.z, xp.w};

    const float* mixes[3] = {mk, mv, mr};
    __nv_bfloat16* outh[3] = {kh, vh, rh};
    __nv_bfloat16* outl[3] = {kl, vl, rl};

#pragma unroll
    for (int s = 0; s < 3; s++) {
        const float4 mx = *(const float4*)(mixes[s] + d);
        const float mxv[4] = {mx.x, mx.y, mx.z, mx.w};
        unsigned short hh[4], ll2[4];
#pragma unroll
        for (int j = 0; j < 4; j++) {
            const float a = xcv[j] * mxv[j] + xpv[j] * (1.0f - mxv[j]);
            __nv_bfloat16 h, lo;
            split1(a, h, lo);
            hh[j] = __bfloat16_as_ushort(h);
            ll2[j] = __bfloat16_as_ushort(lo);
        }
        *(ushort4*)(outh[s] + idx) = make_ushort4(hh[0], hh[1], hh[2], hh[3]);
        *(ushort4*)(outl[s] + idx) = make_ushort4(ll2[0], ll2[1], ll2[2], ll2[3]);
    }
}

__global__ void conv_w(const float* __restrict__ W,
                       __nv_bfloat16* __restrict__ Wh, __nv_bfloat16* __restrict__ Wl)
{
    const size_t gid = (size_t)blockIdx.x * blockDim.x + threadIdx.x;
    const size_t idx = gid * 4;
    const float4 w4 = *(const float4*)(W + idx);
    const float wv[4] = {w4.x, w4.y, w4.z, w4.w};
    unsigned short hh[4], ll2[4];
#pragma unroll
    for (int j = 0; j < 4; j++) {
        __nv_bfloat16 h, lo;
        split1(wv[j], h, lo);
        hh[j] = __bfloat16_as_ushort(h);
        ll2[j] = __bfloat16_as_ushort(lo);
    }
    *(ushort4*)(Wh + idx) = make_ushort4(hh[0], hh[1], hh[2], hh[3]);
    *(ushort4*)(Wl + idx) = make_ushort4(ll2[0], ll2[1], ll2[2], ll2[3]);
}

// ---------------------------------------------------------------------------
// WKV scan (chunk-parallel affine recurrence), NC=64 chunks for occupancy
// ---------------------------------------------------------------------------
__global__ void wkv_phase1(const float* __restrict__ K_,
                           const float* __restrict__ V_,
                           const float* __restrict__ td,
                           float* __restrict__ SA,
                           float* __restrict__ SB)
{
    const int gid = blockIdx.x * blockDim.x + threadIdx.x;
    const int d = gid % DD;
    const int b = (gid / DD) % BB;
    const int c = gid / (DD * BB);

    const float w = -expf(td[d]);
    const float decay = expf(w);

    size_t base = ((size_t)(b * LL + c * CL)) * DD + d;
    float sa = 0.0f, sb = 0.0f;
#pragma unroll 4
    for (int t = 0; t < CL; t++) {
        const float kt = K_[base];
        const float vt = V_[base];
        const float ek = expf(kt);
        sa = decay * sa + ek * vt;
        sb = decay * sb + ek;
        base += DD;
    }
    SA[gid] = sa;
    SB[gid] = sb;
}

__global__ void wkv_phase2(const float* __restrict__ SA,
                           const float* __restrict__ SB,
                           const float* __restrict__ td,
                           float* __restrict__ AIN,
                           float* __restrict__ BIN)
{
    const int gid = blockIdx.x * blockDim.x + threadIdx.x;
    const int d = gid % DD;
    const int b = gid / DD;

    const float w = -expf(td[d]);
    const float dpow = expf(w * (float)CL);

    float a = 0.0f, bs = 0.0f;
#pragma unroll
    for (int c = 0; c < NC; c++) {
        const size_t sidx = ((size_t)c * BB + b) * DD + d;
        AIN[sidx] = a;
        BIN[sidx] = bs;
        a  = dpow * a  + SA[sidx];
        bs = dpow * bs + SB[sidx];
    }
}

__global__ void wkv_phase3(const float* __restrict__ K_,
                           const float* __restrict__ V_,
                           const float* __restrict__ td,
                           const float* __restrict__ tf,
                           const float* __restrict__ AIN,
                           const float* __restrict__ BIN,
                           const float* __restrict__ R,
                           __nv_bfloat16* __restrict__ RWH,
                           __nv_bfloat16* __restrict__ RWL)
{
    const int gid = blockIdx.x * blockDim.x + threadIdx.x;
    const int d = gid % DD;
    const int b = (gid / DD) % BB;
    const int c = gid / (DD * BB);

    const float w = -expf(td[d]);
    const float decay = expf(w);
    const float u = tf[d];

    float a  = AIN[gid];
    float bs = BIN[gid];

    size_t base = ((size_t)(b * LL + c * CL)) * DD + d;
#pragma unroll 4
    for (int t = 0; t < CL; t++) {
        const float kt = K_[base];
        const float vt = V_[base];
        const float eku = expf(u + kt);
        const float wkv = (a + eku * vt) / fmaxf(bs + eku, 1e-6f);
        const float ek = expf(kt);
        const float rw = R[base] * wkv;
        __nv_bfloat16 h, lo;
        split1(rw, h, lo);
        RWH[base] = h;
        RWL[base] = lo;
        a  = decay * a  + ek * vt;
        bs = decay * bs + ek;
        base += DD;
    }
}

// ---------------------------------------------------------------------------
extern "C" void kernel_launch(void* const* d_in, const int* in_sizes, int n_in,
                              void* d_out, int out_size)
{
    const float* x  = (const float*)d_in[0];
    const float* td = (const float*)d_in[1];
    const float* tf = (const float*)d_in[2];
    const float* mk = (const float*)d_in[3];
    const float* mv = (const float*)d_in[4];
    const float* mr = (const float*)d_in[5];
    const float* Wk = (const float*)d_in[6];
    const float* Wv = (const float*)d_in[7];
    const float* Wr = (const float*)d_in[8];
    const float* Wo = (const float*)d_in[9];
    float* out = (float*)d_out;

    float *gk, *gv, *gr, *gsa, *gsb, *gain, *gbin;
    __nv_bfloat16 *xkh, *xkl, *xvh, *xvl, *xrh, *xrl, *rwh, *rwl, *wh, *wl;
    cudaGetSymbolAddress((void**)&gk,   g_k);
    cudaGetSymbolAddress((void**)&gv,   g_v);
    cudaGetSymbolAddress((void**)&gr,   g_r);
    cudaGetSymbolAddress((void**)&gsa,  g_sa);
    cudaGetSymbolAddress((void**)&gsb,  g_sb);
    cudaGetSymbolAddress((void**)&gain, g_ain);
    cudaGetSymbolAddress((void**)&gbin, g_bin);
    cudaGetSymbolAddress((void**)&xkh,  g_xkh);
    cudaGetSymbolAddress((void**)&xkl,  g_xkl);
    cudaGetSymbolAddress((void**)&xvh,  g_xvh);
    cudaGetSymbolAddress((void**)&xvl,  g_xvl);
    cudaGetSymbolAddress((void**)&xrh,  g_xrh);
    cudaGetSymbolAddress((void**)&xrl,  g_xrl);
    cudaGetSymbolAddress((void**)&rwh,  g_rwh);
    cudaGetSymbolAddress((void**)&rwl,  g_rwl);
    cudaGetSymbolAddress((void**)&wh,   g_wh);
    cudaGetSymbolAddress((void**)&wl,   g_wl);

    cudaFuncSetAttribute(gemm_bf16<false>,
                         cudaFuncAttributeMaxDynamicSharedMemorySize, GEMM_SMEM_BYTES);
    cudaFuncSetAttribute(gemm_bf16<true>,
                         cudaFuncAttributeMaxDynamicSharedMemorySize, GEMM_SMEM_BYTES);

    const size_t WSTRIDE = (size_t)DD * DD;

    // conversions
    conv_x<<<(int)(((size_t)MM * DD / 4) / 256), 256>>>(x, mk, mv, mr,
                                                        xkh, xkl, xvh, xvl, xrh, xrl);
    conv_w<<<(int)((WSTRIDE / 4) / 256), 256>>>(Wk, wh + 0 * WSTRIDE, wl + 0 * WSTRIDE);
    conv_w<<<(int)((WSTRIDE / 4) / 256), 256>>>(Wv, wh + 1 * WSTRIDE, wl + 1 * WSTRIDE);
    conv_w<<<(int)((WSTRIDE / 4) / 256), 256>>>(Wr, wh + 2 * WSTRIDE, wl + 2 * WSTRIDE);
    conv_w<<<(int)((WSTRIDE / 4) / 256), 256>>>(Wo, wh + 3 * WSTRIDE, wl + 3 * WSTRIDE);

    const dim3 gg(DD / 128, MM / 128);

    // projections
    gemm_bf16<false><<<gg, 256, GEMM_SMEM_BYTES>>>(xkh, xkl, wh + 0 * WSTRIDE, wl + 0 * WSTRIDE, gk);
    gemm_bf16<false><<<gg, 256, GEMM_SMEM_BYTES>>>(xvh, xvl, wh + 1 * WSTRIDE, wl + 1 * WSTRIDE, gv);
    gemm_bf16<true ><<<gg, 256, GEMM_SMEM_BYTES>>>(xrh, xrl, wh + 2 * WSTRIDE, wl + 2 * WSTRIDE, gr);

    // wkv scan
    wkv_phase1<<<(NC * BB * DD) / 256, 256>>>(gk, gv, td, gsa, gsb);
    wkv_phase2<<<(BB * DD) / 256, 256>>>(gsa, gsb, td, gain, gbin);
    wkv_phase3<<<(NC * BB * DD) / 256, 256>>>(gk, gv, td, tf, gain, gbin, gr, rwh, rwl);

    // output projection
    gemm_bf16<false><<<gg, 256, GEMM_SMEM_BYTES>>>(rwh, rwl, wh + 3 * WSTRIDE, wl + 3 * WSTRIDE, out);
}

// round 9
// speedup vs baseline: 3.7423x; 1.3365x over previous
#include <cuda_runtime.h>
#include <cuda_fp16.h>
#include <math.h>
#include <cstdint>
#include <cstddef>

// Problem constants
constexpr int BB = 4;
constexpr int LL = 4096;
constexpr int DD = 1024;
constexpr int MM = BB * LL;           // 16384 rows
constexpr int NC = 64;                // scan chunks
constexpr int CL = LL / NC;           // 64 steps per chunk

// ---------------------------------------------------------------------------
// Static device scratch (no allocations allowed)
// ---------------------------------------------------------------------------
__device__ float g_k[(size_t)MM * DD];
__device__ float g_v[(size_t)MM * DD];
__device__ float g_r[(size_t)MM * DD];

__device__ __half g_xkh[(size_t)MM * DD];
__device__ __half g_xkl[(size_t)MM * DD];
__device__ __half g_xvh[(size_t)MM * DD];
__device__ __half g_xvl[(size_t)MM * DD];
__device__ __half g_xrh[(size_t)MM * DD];
__device__ __half g_xrl[(size_t)MM * DD];
__device__ __half g_rwh[(size_t)MM * DD];
__device__ __half g_rwl[(size_t)MM * DD];

__device__ __half g_wh[4][(size_t)DD * DD];
__device__ __half g_wl[4][(size_t)DD * DD];

__device__ float g_sa[NC * BB * DD];
__device__ float g_sb[NC * BB * DD];
__device__ float g_ain[NC * BB * DD];
__device__ float g_bin[NC * BB * DD];

// ---------------------------------------------------------------------------
// PTX helpers (arch-portable: cp.async / ldmatrix / mma.sync)
// ---------------------------------------------------------------------------
__device__ __forceinline__ uint32_t smem_u32(const void* p) {
    uint32_t a;
    asm("{ .reg .u64 t; cvta.to.shared.u64 t, %1; cvt.u32.u64 %0, t; }"
        : "=r"(a) : "l"(p));
    return a;
}

__device__ __forceinline__ void cp16(uint32_t dst, const void* src) {
    asm volatile("cp.async.cg.shared.global [%0], [%1], 16;"
                 :: "r"(dst), "l"(src) : "memory");
}

__device__ __forceinline__ void cp_commit() {
    asm volatile("cp.async.commit_group;" ::: "memory");
}

template <int N>
__device__ __forceinline__ void cp_wait() {
    asm volatile("cp.async.wait_group %0;" :: "n"(N) : "memory");
}

__device__ __forceinline__ void ldsm4(uint32_t* r, uint32_t addr) {
    asm volatile("ldmatrix.sync.aligned.m8n8.x4.shared.b16 {%0,%1,%2,%3}, [%4];"
                 : "=r"(r[0]), "=r"(r[1]), "=r"(r[2]), "=r"(r[3]) : "r"(addr));
}

__device__ __forceinline__ void mma_f16(float* d, const uint32_t* a, const uint32_t* b) {
    asm volatile(
        "mma.sync.aligned.m16n8k16.row.col.f32.f16.f16.f32 "
        "{%0,%1,%2,%3}, {%4,%5,%6,%7}, {%8,%9}, {%0,%1,%2,%3};"
        : "+f"(d[0]), "+f"(d[1]), "+f"(d[2]), "+f"(d[3])
        : "r"(a[0]), "r"(a[1]), "r"(a[2]), "r"(a[3]), "r"(b[0]), "r"(b[1]));
}

__device__ __forceinline__ void split1(float a, __half& h, __half& l) {
    h = __float2half_rn(a);
    l = __float2half_rn(a - __half2float(h));
}

// Swizzled smem offset for a [128 x 32] fp16 tile (rows of 4 x 16B chunks).
// 128B lines hold two rows; 8 chunk-positions per line XORed with line&7.
// Conflict-free for ldmatrix (8 consecutive rows, fixed chunk col).
__device__ __forceinline__ uint32_t phys(int r, int c) {
    return (uint32_t)((r >> 1) * 128 + ((((r & 1) * 4 + c) ^ ((r >> 1) & 7)) * 16));
}

// ---------------------------------------------------------------------------
// fp16 split GEMM via mma.sync:  C[m][n] = sum_k A[m][k]*W[n][k]
//   NPASS=3: C = Ah*Wh + Al*Wh + Ah*Wl   (residual ~2^-22, for k projection)
//   NPASS=2: C = Ah*Wh + Al*Wh           (err ~2.8e-4 RMS, for v/r/o)
// CTA tile 128x128, BK=32, 256 threads (8 warps, 2M x 4N), 4-stage ring.
// Pass-major MMA order: same-acc RAW distance = 16 MMAs.
// ---------------------------------------------------------------------------
constexpr int TILE_BYTES = 128 * 32 * 2;           // 8192
constexpr int PIPE = 4;
constexpr int NSTAGE = DD / 32;                    // 32

#define STAGE_BYTES_OF(np)  (((np) + 1) * TILE_BYTES)
#define GEMM_SMEM_OF(np)    (PIPE * STAGE_BYTES_OF(np))

template <int NPASS, bool SIG>
__global__ void __launch_bounds__(256)
gemm_f16(const __half* __restrict__ Ah, const __half* __restrict__ Al,
         const __half* __restrict__ Wh, const __half* __restrict__ Wl,
         float* __restrict__ C)
{
    constexpr int SBYTES = (NPASS + 1) * TILE_BYTES;
    constexpr int OFF_AH = 0;
    constexpr int OFF_AL = TILE_BYTES;
    constexpr int OFF_WH = 2 * TILE_BYTES;
    constexpr int OFF_WL = 3 * TILE_BYTES;   // only used when NPASS==3

    extern __shared__ char smem[];
    const uint32_t sb = smem_u32(smem);
    const int tid = threadIdx.x;
    const int wid = tid >> 5;
    const int l   = tid & 31;
    const int wm  = wid & 1;          // 0..1 (M)
    const int wn  = wid >> 1;         // 0..3 (N)
    const int bm  = blockIdx.y * 128;
    const int bn  = blockIdx.x * 128;

    // ---- loader mapping: each thread copies 2 x 16B chunks per tile ----
    const int lr = tid >> 1;                   // 0..127
    const int lc0 = (tid & 1) * 2;             // chunk 0 or 2
    const size_t arow = (size_t)(bm + lr) * DD;
    const size_t wrow = (size_t)(bn + lr) * DD;
    const uint32_t sw0 = phys(lr, lc0);
    const uint32_t sw1 = phys(lr, lc0 + 1);

    float acc[4][4][4];
#pragma unroll
    for (int i = 0; i < 4; i++)
#pragma unroll
        for (int j = 0; j < 4; j++)
#pragma unroll
            for (int e = 0; e < 4; e++) acc[i][j][e] = 0.0f;

    auto load_stage = [&](int buf, int kc) {
        const uint32_t base = sb + buf * SBYTES;
        const __half* pa_h = Ah + arow + kc + lc0 * 8;
        const __half* pa_l = Al + arow + kc + lc0 * 8;
        const __half* pw_h = Wh + wrow + kc + lc0 * 8;
        cp16(base + OFF_AH + sw0, pa_h);
        cp16(base + OFF_AH + sw1, pa_h + 8);
        cp16(base + OFF_AL + sw0, pa_l);
        cp16(base + OFF_AL + sw1, pa_l + 8);
        cp16(base + OFF_WH + sw0, pw_h);
        cp16(base + OFF_WH + sw1, pw_h + 8);
        if (NPASS == 3) {
            const __half* pw_l = Wl + wrow + kc + lc0 * 8;
            cp16(base + OFF_WL + sw0, pw_l);
            cp16(base + OFF_WL + sw1, pw_l + 8);
        }
    };

    // ---- ldmatrix lane-address components ----
    const int ra = wm * 64 + (l & 7) + ((l >> 3) & 1) * 8;   // + mt*16
    const int ca = (l >> 4) & 1;                              // + ks*2
    const int rb = wn * 32 + (l & 7) + ((l >> 4) & 1) * 8;   // + nt2*16
    const int cb = (l >> 3) & 1;                              // + ks*2

    // ---- preload PIPE-1 stages ----
#pragma unroll
    for (int i = 0; i < PIPE - 1; i++) {
        load_stage(i, i * 32);
        cp_commit();
    }

    for (int s = 0; s < NSTAGE; s++) {
        cp_wait<PIPE - 2>();
        __syncthreads();

        if (s + PIPE - 1 < NSTAGE)
            load_stage((s + PIPE - 1) & (PIPE - 1), (s + PIPE - 1) * 32);
        cp_commit();

        const uint32_t base = sb + (s & (PIPE - 1)) * SBYTES;
#pragma unroll
        for (int ks = 0; ks < 2; ks++) {
            uint32_t ah[16], al[16], wh8[8], wl8[8];
#pragma unroll
            for (int mt = 0; mt < 4; mt++) {
                const uint32_t off = phys(ra + mt * 16, ks * 2 + ca);
                ldsm4(ah + mt * 4, base + OFF_AH + off);
                ldsm4(al + mt * 4, base + OFF_AL + off);
            }
#pragma unroll
            for (int nt2 = 0; nt2 < 2; nt2++) {
                const uint32_t off = phys(rb + nt2 * 16, ks * 2 + cb);
                ldsm4(wh8 + nt2 * 4, base + OFF_WH + off);
                if (NPASS == 3) ldsm4(wl8 + nt2 * 4, base + OFF_WL + off);
            }
            // pass-major: same-acc MMAs are 16 apart (no RAW back-pressure)
#pragma unroll
            for (int mt = 0; mt < 4; mt++)
#pragma unroll
                for (int nt = 0; nt < 4; nt++)
                    mma_f16(acc[mt][nt], ah + mt * 4, wh8 + nt * 2);
#pragma unroll
            for (int mt = 0; mt < 4; mt++)
#pragma unroll
                for (int nt = 0; nt < 4; nt++)
                    mma_f16(acc[mt][nt], al + mt * 4, wh8 + nt * 2);
            if (NPASS == 3) {
#pragma unroll
                for (int mt = 0; mt < 4; mt++)
#pragma unroll
                    for (int nt = 0; nt < 4; nt++)
                        mma_f16(acc[mt][nt], ah + mt * 4, wl8 + nt * 2);
            }
        }
    }

    // ---- epilogue ----
    const int er = l >> 2;            // 0..7
    const int ec = (l & 3) * 2;       // 0,2,4,6
#pragma unroll
    for (int mt = 0; mt < 4; mt++) {
#pragma unroll
        for (int nt = 0; nt < 4; nt++) {
            const int m0 = bm + wm * 64 + mt * 16 + er;
            const int n0 = bn + wn * 32 + nt * 8 + ec;
            float v0 = acc[mt][nt][0], v1 = acc[mt][nt][1];
            float v2 = acc[mt][nt][2], v3 = acc[mt][nt][3];
            if (SIG) {
                v0 = 1.0f / (1.0f + __expf(-v0));
                v1 = 1.0f / (1.0f + __expf(-v1));
                v2 = 1.0f / (1.0f + __expf(-v2));
                v3 = 1.0f / (1.0f + __expf(-v3));
            }
            *(float2*)(C + (size_t)m0 * DD + n0)       = make_float2(v0, v1);
            *(float2*)(C + (size_t)(m0 + 8) * DD + n0) = make_float2(v2, v3);
        }
    }
}

// ---------------------------------------------------------------------------
// Conversion: token-shift mix + fp16 hi/lo split for the three projections
// ---------------------------------------------------------------------------
__global__ void conv_x(const float* __restrict__ x,
                       const float* __restrict__ mk, const float* __restrict__ mv,
                       const float* __restrict__ mr,
                       __half* __restrict__ kh, __half* __restrict__ kl,
                       __half* __restrict__ vh, __half* __restrict__ vl,
                       __half* __restrict__ rh, __half* __restrict__ rl)
{
    const size_t gid = (size_t)blockIdx.x * blockDim.x + threadIdx.x;
    const size_t idx = gid * 4;
    const int d = (int)(idx % DD);
    const size_t m = idx / DD;
    const int lpos = (int)(m & (LL - 1));

    const float4 xc = *(const float4*)(x + idx);
    float4 xp = make_float4(0.f, 0.f, 0.f, 0.f);
    if (lpos != 0) xp = *(const float4*)(x + idx - DD);

    const float xcv[4] = {xc.x, xc.y, xc.z, xc.w};
    const float xpv[4] = {xp.x, xp.y, xp.z, xp.w};

    const float* mixes[3] = {mk, mv, mr};
    __half* outh[3] = {kh, vh, rh};
    __half* outl[3] = {kl, vl, rl};

#pragma unroll
    for (int s = 0; s < 3; s++) {
        const float4 mx = *(const float4*)(mixes[s] + d);
        const float mxv[4] = {mx.x, mx.y, mx.z, mx.w};
        unsigned short hh[4], ll2[4];
#pragma unroll
        for (int j = 0; j < 4; j++) {
            const float a = xcv[j] * mxv[j] + xpv[j] * (1.0f - mxv[j]);
            __half h, lo;
            split1(a, h, lo);
            hh[j] = __half_as_ushort(h);
            ll2[j] = __half_as_ushort(lo);
        }
        *(ushort4*)(outh[s] + idx) = make_ushort4(hh[0], hh[1], hh[2], hh[3]);
        *(ushort4*)(outl[s] + idx) = make_ushort4(ll2[0], ll2[1], ll2[2], ll2[3]);
    }
}

// All 4 weight matrices in one kernel (fp16 hi/lo)
__global__ void conv_w_all(const float* __restrict__ W0, const float* __restrict__ W1,
                           const float* __restrict__ W2, const float* __restrict__ W3,
                           __half* __restrict__ WH, __half* __restrict__ WL)
{
    constexpr size_t WS = (size_t)DD * DD;
    const size_t gid = (size_t)blockIdx.x * blockDim.x + threadIdx.x;
    const size_t idx = gid * 4;                 // over 4*WS elements
    const int mat = (int)(idx / WS);
    const size_t off = idx % WS;
    const float* W = (mat == 0) ? W0 : (mat == 1) ? W1 : (mat == 2) ? W2 : W3;

    const float4 w4 = *(const float4*)(W + off);
    const float wv[4] = {w4.x, w4.y, w4.z, w4.w};
    unsigned short hh[4], ll2[4];
#pragma unroll
    for (int j = 0; j < 4; j++) {
        __half h, lo;
        split1(wv[j], h, lo);
        hh[j] = __half_as_ushort(h);
        ll2[j] = __half_as_ushort(lo);
    }
    *(ushort4*)(WH + idx) = make_ushort4(hh[0], hh[1], hh[2], hh[3]);
    *(ushort4*)(WL + idx) = make_ushort4(ll2[0], ll2[1], ll2[2], ll2[3]);
}

// ---------------------------------------------------------------------------
// WKV scan (chunk-parallel affine recurrence), NC=64 chunks
// ---------------------------------------------------------------------------
__global__ void wkv_phase1(const float* __restrict__ K_,
                           const float* __restrict__ V_,
                           const float* __restrict__ td,
                           float* __restrict__ SA,
                           float* __restrict__ SB)
{
    const int gid = blockIdx.x * blockDim.x + threadIdx.x;
    const int d = gid % DD;
    const int b = (gid / DD) % BB;
    const int c = gid / (DD * BB);

    const float w = -expf(td[d]);
    const float decay = expf(w);

    size_t base = ((size_t)(b * LL + c * CL)) * DD + d;
    float sa = 0.0f, sb = 0.0f;
#pragma unroll 4
    for (int t = 0; t < CL; t++) {
        const float kt = K_[base];
        const float vt = V_[base];
        const float ek = expf(kt);
        sa = decay * sa + ek * vt;
        sb = decay * sb + ek;
        base += DD;
    }
    SA[gid] = sa;
    SB[gid] = sb;
}

__global__ void wkv_phase2(const float* __restrict__ SA,
                           const float* __restrict__ SB,
                           const float* __restrict__ td,
                           float* __restrict__ AIN,
                           float* __restrict__ BIN)
{
    const int gid = blockIdx.x * blockDim.x + threadIdx.x;
    const int d = gid % DD;
    const int b = gid / DD;

    const float w = -expf(td[d]);
    const float dpow = expf(w * (float)CL);

    float a = 0.0f, bs = 0.0f;
#pragma unroll
    for (int c = 0; c < NC; c++) {
        const size_t sidx = ((size_t)c * BB + b) * DD + d;
        AIN[sidx] = a;
        BIN[sidx] = bs;
        a  = dpow * a  + SA[sidx];
        bs = dpow * bs + SB[sidx];
    }
}

__global__ void wkv_phase3(const float* __restrict__ K_,
                           const float* __restrict__ V_,
                           const float* __restrict__ td,
                           const float* __restrict__ tf,
                           const float* __restrict__ AIN,
                           const float* __restrict__ BIN,
                           const float* __restrict__ R,
                           __half* __restrict__ RWH,
                           __half* __restrict__ RWL)
{
    const int gid = blockIdx.x * blockDim.x + threadIdx.x;
    const int d = gid % DD;
    const int b = (gid / DD) % BB;
    const int c = gid / (DD * BB);

    const float w = -expf(td[d]);
    const float decay = expf(w);
    const float u = tf[d];

    float a  = AIN[gid];
    float bs = BIN[gid];

    size_t base = ((size_t)(b * LL + c * CL)) * DD + d;
#pragma unroll 4
    for (int t = 0; t < CL; t++) {
        const float kt = K_[base];
        const float vt = V_[base];
        const float eku = expf(u + kt);
        const float wkv = (a + eku * vt) / fmaxf(bs + eku, 1e-6f);
        const float ek = expf(kt);
        const float rw = R[base] * wkv;
        __half h, lo;
        split1(rw, h, lo);
        RWH[base] = h;
        RWL[base] = lo;
        a  = decay * a  + ek * vt;
        bs = decay * bs + ek;
        base += DD;
    }
}

// ---------------------------------------------------------------------------
extern "C" void kernel_launch(void* const* d_in, const int* in_sizes, int n_in,
                              void* d_out, int out_size)
{
    const float* x  = (const float*)d_in[0];
    const float* td = (const float*)d_in[1];
    const float* tf = (const float*)d_in[2];
    const float* mk = (const float*)d_in[3];
    const float* mv = (const float*)d_in[4];
    const float* mr = (const float*)d_in[5];
    const float* Wk = (const float*)d_in[6];
    const float* Wv = (const float*)d_in[7];
    const float* Wr = (const float*)d_in[8];
    const float* Wo = (const float*)d_in[9];
    float* out = (float*)d_out;

    float *gk, *gv, *gr, *gsa, *gsb, *gain, *gbin;
    __half *xkh, *xkl, *xvh, *xvl, *xrh, *xrl, *rwh, *rwl, *wh, *wl;
    cudaGetSymbolAddress((void**)&gk,   g_k);
    cudaGetSymbolAddress((void**)&gv,   g_v);
    cudaGetSymbolAddress((void**)&gr,   g_r);
    cudaGetSymbolAddress((void**)&gsa,  g_sa);
    cudaGetSymbolAddress((void**)&gsb,  g_sb);
    cudaGetSymbolAddress((void**)&gain, g_ain);
    cudaGetSymbolAddress((void**)&gbin, g_bin);
    cudaGetSymbolAddress((void**)&xkh,  g_xkh);
    cudaGetSymbolAddress((void**)&xkl,  g_xkl);
    cudaGetSymbolAddress((void**)&xvh,  g_xvh);
    cudaGetSymbolAddress((void**)&xvl,  g_xvl);
    cudaGetSymbolAddress((void**)&xrh,  g_xrh);
    cudaGetSymbolAddress((void**)&xrl,  g_xrl);
    cudaGetSymbolAddress((void**)&rwh,  g_rwh);
    cudaGetSymbolAddress((void**)&rwl,  g_rwl);
    cudaGetSymbolAddress((void**)&wh,   g_wh);
    cudaGetSymbolAddress((void**)&wl,   g_wl);

    cudaFuncSetAttribute(gemm_f16<3, false>,
                         cudaFuncAttributeMaxDynamicSharedMemorySize, GEMM_SMEM_OF(3));
    cudaFuncSetAttribute(gemm_f16<2, false>,
                         cudaFuncAttributeMaxDynamicSharedMemorySize, GEMM_SMEM_OF(2));
    cudaFuncSetAttribute(gemm_f16<2, true>,
                         cudaFuncAttributeMaxDynamicSharedMemorySize, GEMM_SMEM_OF(2));

    const size_t WSTRIDE = (size_t)DD * DD;
    const dim3 gg(DD / 128, MM / 128);

    // launch 0: conv_x, 1: conv_w_all
    conv_x<<<(int)(((size_t)MM * DD / 4) / 256), 256>>>(x, mk, mv, mr,
                                                        xkh, xkl, xvh, xvl, xrh, xrl);
    conv_w_all<<<(int)((4 * WSTRIDE / 4) / 256), 256>>>(Wk, Wv, Wr, Wo, wh, wl);

    // launch 2: k (3-pass, feeds exp), 3: v (2-pass, profiled slot), 4: r (2-pass)
    gemm_f16<3, false><<<gg, 256, GEMM_SMEM_OF(3)>>>(xkh, xkl, wh + 0 * WSTRIDE, wl + 0 * WSTRIDE, gk);
    gemm_f16<2, false><<<gg, 256, GEMM_SMEM_OF(2)>>>(xvh, xvl, wh + 1 * WSTRIDE, nullptr, gv);
    gemm_f16<2, true ><<<gg, 256, GEMM_SMEM_OF(2)>>>(xrh, xrl, wh + 2 * WSTRIDE, nullptr, gr);

    // launches 5-7: wkv scan
    wkv_phase1<<<(NC * BB * DD) / 256, 256>>>(gk, gv, td, gsa, gsb);
    wkv_phase2<<<(BB * DD) / 256, 256>>>(gsa, gsb, td, gain, gbin);
    wkv_phase3<<<(NC * BB * DD) / 256, 256>>>(gk, gv, td, tf, gain, gbin, gr, rwh, rwl);

    // launch 8: output projection (2-pass)
    gemm_f16<2, false><<<gg, 256, GEMM_SMEM_OF(2)>>>(rwh, rwl, wh + 3 * WSTRIDE, nullptr, out);
}